// round 2
// baseline (speedup 1.0000x reference)
#include <cuda_runtime.h>
#include <cstdint>

// Problem constants
#define Nn   8192
#define Dd   256
#define Kk   32
#define GRID 152
#define TPB  256
#define RI   8            // rows staged per iteration (== warps per block)
#define NCH  (Nn / RI)    // 1024 chunks

typedef unsigned long long ull;

// ---------- scratch (static device memory; no allocation) ----------
__device__ float g_coefA[Dd * Kk];            // a[d][k] = w^2 - 1
__device__ float g_coefC[Dd * Kk];            // c[d][k] = 2 w^2 b
__device__ float g_e[Kk];                     // e[k]    = sum_d w^2 b^2
__device__ float g_part[GRID][2 * Kk * Dd];   // per-block partial G1|G2, [d][k] layout
__device__ float g_g0[GRID * Kk];             // per-block partial G0

// ---------- packed f32x2 helpers ----------
__device__ __forceinline__ ull ffma2(ull a, ull b, ull c) {
    ull d;
    asm("fma.rn.f32x2 %0, %1, %2, %3;" : "=l"(d) : "l"(a), "l"(b), "l"(c));
    return d;
}
__device__ __forceinline__ ull pack2(float lo, float hi) {
    ull r;
    asm("mov.b64 %0, {%1, %2};" : "=l"(r) : "f"(lo), "f"(hi));
    return r;
}
__device__ __forceinline__ void unpack2(ull v, float& lo, float& hi) {
    asm("mov.b64 {%0, %1}, %2;" : "=f"(lo), "=f"(hi) : "l"(v));
}

// ---------- prep: build coefficient tables ----------
__global__ void prep_kernel(const float* __restrict__ w, const float* __restrict__ b) {
    int k = blockIdx.x;     // 0..31
    int d = threadIdx.x;    // 0..255
    float wv = w[k * Dd + d];
    float bv = b[k * Dd + d];
    float w2 = wv * wv;
    g_coefA[d * Kk + k] = w2 - 1.0f;
    g_coefC[d * Kk + k] = 2.0f * w2 * bv;

    __shared__ float sr[TPB];
    sr[d] = w2 * bv * bv;
    __syncthreads();
    for (int s = 128; s > 0; s >>= 1) {
        if (d < s) sr[d] += sr[d + s];
        __syncthreads();
    }
    if (d == 0) g_e[k] = sr[0];
}

// ---------- main: fused gamma + G-statistics over one pass of x ----------
__global__ __launch_bounds__(TPB, 1) void main_kernel(const float* __restrict__ x) {
    __shared__ float xs[RI * Dd];        // 8 KB staged rows
    __shared__ float x2s[RI * Dd];       // 8 KB staged squares
    __shared__ float red[RI * 8 * Kk];   // 8 KB y4 partials [r][w][k]
    __shared__ float gam[RI * Kk];       // 1 KB gamma [r][k]
    __shared__ float es[Kk];

    const int t  = threadIdx.x;
    const int w  = t >> 5;    // warp id -> d-slice
    const int k  = t & 31;    // lane -> mixture component
    const int d0 = w * 32;

    // per-thread coefficient registers (packed d-pairs)
    ull a2[16], c2[16];
#pragma unroll
    for (int i = 0; i < 16; i++) {
        a2[i] = pack2(g_coefA[(d0 + 2 * i) * Kk + k], g_coefA[(d0 + 2 * i + 1) * Kk + k]);
        c2[i] = pack2(g_coefC[(d0 + 2 * i) * Kk + k], g_coefC[(d0 + 2 * i + 1) * Kk + k]);
    }
    if (t < Kk) es[t] = g_e[t];

    // per-thread accumulators for G1, G2 (packed d-pairs)
    ull acc1[16], acc2[16];
#pragma unroll
    for (int i = 0; i < 16; i++) { acc1[i] = 0ull; acc2[i] = 0ull; }
    float g0acc = 0.0f;

    const float4* xg = reinterpret_cast<const float4*>(x);
    float4* xs4  = reinterpret_cast<float4*>(xs);
    float4* x2s4 = reinterpret_cast<float4*>(x2s);

    int c = blockIdx.x;
    float4 r0, r1;
    // prefetch first chunk (RI*Dd/4 = 512 float4 per chunk)
    r0 = xg[c * 512 + t];
    r1 = xg[c * 512 + t + 256];

    for (; c < NCH; c += GRID) {
        // stage current chunk (+ squares)
        xs4[t]        = r0;
        xs4[t + 256]  = r1;
        float4 q0 = make_float4(r0.x * r0.x, r0.y * r0.y, r0.z * r0.z, r0.w * r0.w);
        float4 q1 = make_float4(r1.x * r1.x, r1.y * r1.y, r1.z * r1.z, r1.w * r1.w);
        x2s4[t]       = q0;
        x2s4[t + 256] = q1;
        __syncthreads();

        // prefetch next chunk; LDG latency overlaps phases A/B
        int nc = c + GRID;
        if (nc < NCH) {
            r0 = xg[nc * 512 + t];
            r1 = xg[nc * 512 + t + 256];
        }

        // ---- phase A: partial logits t_k = sum_d (a*x^2 + c*x) over this warp's d-slice
#pragma unroll
        for (int r = 0; r < RI; r++) {
            ull ta = 0ull, tc = 0ull;
            const float* xr  = &xs[r * Dd + d0];
            const float* x2r = &x2s[r * Dd + d0];
#pragma unroll
            for (int i = 0; i < 8; i++) {
                double2 vx = *reinterpret_cast<const double2*>(xr + 4 * i);
                double2 v2 = *reinterpret_cast<const double2*>(x2r + 4 * i);
                ta = ffma2(a2[2 * i],     __double_as_longlong(v2.x), ta);
                ta = ffma2(a2[2 * i + 1], __double_as_longlong(v2.y), ta);
                tc = ffma2(c2[2 * i],     __double_as_longlong(vx.x), tc);
                tc = ffma2(c2[2 * i + 1], __double_as_longlong(vx.y), tc);
            }
            float alo, ahi, clo, chi;
            unpack2(ta, alo, ahi);
            unpack2(tc, clo, chi);
            red[r * 256 + w * 32 + k] = (alo + ahi) + (clo + chi);
        }
        __syncthreads();

        // ---- softmax: warp w owns staged row w; lane = k
        {
            int r = w;
            float s = 0.0f;
#pragma unroll
            for (int j = 0; j < 8; j++) s += red[r * 256 + j * 32 + k];
            float lg = -0.5f * (s + es[k]);
            float m = lg;
#pragma unroll
            for (int o = 16; o > 0; o >>= 1)
                m = fmaxf(m, __shfl_xor_sync(0xffffffffu, m, o));
            float p = __expf(lg - m);
            float sm = p;
#pragma unroll
            for (int o = 16; o > 0; o >>= 1)
                sm += __shfl_xor_sync(0xffffffffu, sm, o);
            float g = p / sm;
            gam[r * Kk + k] = g;
            g0acc += g;
        }
        __syncthreads();

        // ---- phase B: accumulate G1 += gamma*x, G2 += gamma*x^2
#pragma unroll
        for (int r = 0; r < RI; r++) {
            float g = gam[r * Kk + k];
            ull g2 = pack2(g, g);
            const float* xr  = &xs[r * Dd + d0];
            const float* x2r = &x2s[r * Dd + d0];
#pragma unroll
            for (int i = 0; i < 8; i++) {
                double2 vx = *reinterpret_cast<const double2*>(xr + 4 * i);
                double2 v2 = *reinterpret_cast<const double2*>(x2r + 4 * i);
                acc1[2 * i]     = ffma2(g2, __double_as_longlong(vx.x), acc1[2 * i]);
                acc1[2 * i + 1] = ffma2(g2, __double_as_longlong(vx.y), acc1[2 * i + 1]);
                acc2[2 * i]     = ffma2(g2, __double_as_longlong(v2.x), acc2[2 * i]);
                acc2[2 * i + 1] = ffma2(g2, __double_as_longlong(v2.y), acc2[2 * i + 1]);
            }
        }
        __syncthreads();  // protect xs before next staging
    }

    // ---- write per-block partials (coalesced: [d][k] layout)
    float* P = g_part[blockIdx.x];
#pragma unroll
    for (int i = 0; i < 16; i++) {
        float lo, hi;
        unpack2(acc1[i], lo, hi);
        P[(d0 + 2 * i) * Kk + k]     = lo;
        P[(d0 + 2 * i + 1) * Kk + k] = hi;
        unpack2(acc2[i], lo, hi);
        P[8192 + (d0 + 2 * i) * Kk + k]     = lo;
        P[8192 + (d0 + 2 * i + 1) * Kk + k] = hi;
    }

    // ---- G0 partial: reduce 8 warps' lane-k sums
    __syncthreads();
    red[w * 32 + k] = g0acc;
    __syncthreads();
    if (w == 0) {
        float s = 0.0f;
#pragma unroll
        for (int j = 0; j < 8; j++) s += red[j * 32 + k];
        g_g0[blockIdx.x * Kk + k] = s;
    }
}

// ---------- finalize: cross-block reduce + epilogue transform ----------
__global__ void finalize_kernel(const float* __restrict__ w, const float* __restrict__ b,
                                float* __restrict__ out) {
    __shared__ float sG0[Kk];
    int t = threadIdx.x;
    if (t < Kk) {
        float s = 0.0f;
        for (int p = 0; p < GRID; p++) s += g_g0[p * Kk + t];
        sG0[t] = s;
    }
    __syncthreads();

    int e = blockIdx.x * 256 + t;   // 0..8191, e = d*32 + k
    int d = e >> 5;
    int k = e & 31;

    float s1 = 0.0f, s2 = 0.0f;
    for (int p = 0; p < GRID; p++) {
        s1 += g_part[p][e];
        s2 += g_part[p][8192 + e];
    }

    float wv = w[k * Dd + d];
    float bv = b[k * Dd + d];
    float G0 = sG0[k];
    const float invN = 1.0f / (float)Nn;

    float mu = wv * (s1 + bv * G0) * invN;
    float w2 = wv * wv;
    float m2 = w2 * (s2 + 2.0f * bv * s1 + bv * bv * G0);
    float sig = (m2 - G0) * (invN * 0.70710678118654752440f);

    out[k * Dd + d]        = sig;   // sigma part
    out[8192 + k * Dd + d] = mu;    // mu part
}

extern "C" void kernel_launch(void* const* d_in, const int* in_sizes, int n_in,
                              void* d_out, int out_size) {
    const float* x = (const float*)d_in[0];
    const float* w = (const float*)d_in[1];
    const float* b = (const float*)d_in[2];
    float* out = (float*)d_out;

    prep_kernel<<<Kk, Dd>>>(w, b);
    main_kernel<<<GRID, TPB>>>(x);
    finalize_kernel<<<32, 256>>>(w, b, out);
}